// round 10
// baseline (speedup 1.0000x reference)
#include <cuda_runtime.h>
#include <math.h>

#define BATCH   8
#define NPTS    4096
#define NBINS   128
#define CAP     256                    // >= +15 sigma of expected ~102/bin
#define XMIN    (-4.25f)
#define XSPAN   8.5f
#define BINW    (XSPAN / NBINS)
#define BININV  (NBINS / XSPAN)
#define NARR    (2 * BATCH)            // 16 bucketed arrays (pred x8, target x8)
#define QPB     256                    // queries per scan block
#define NCHUNK  (NPTS / QPB)           // 16
#define GRID3   (2 * BATCH * NCHUNK)   // 256 scan blocks
#define SMEM3   (NPTS * 16 + 2 * NBINS * 4)   // cand[4096] + two prefix arrays

__device__ float4   g_bins[NARR * NBINS * CAP];   // (t2, -2x, -2y, -2z), 8 MB
__device__ int      g_cnt [NARR * NBINS];         // bin cursors/counts
__device__ float    g_bsum[GRID3];
__device__ unsigned g_tick;                       // zero-init; self-reset

// ---- K1: zero bin cursors ------------------------------------------------
__global__ void zero_kernel() {
    for (int k = threadIdx.x; k < NARR * NBINS; k += 256) g_cnt[k] = 0;
}

// ---- K2: scatter points into x-bins (transformed quads) ------------------
__global__ __launch_bounds__(256)
void scatter_kernel(const float* __restrict__ pred,
                    const float* __restrict__ target)
{
    int idx = blockIdx.x * 256 + threadIdx.x;   // 0..65535
    int i = idx & (NPTS - 1);
    int b = (idx >> 12) & 7;
    int s = idx >> 15;                           // 0=pred, 1=target
    const float* p = (s ? target : pred) + ((size_t)b * NPTS + i) * 3;
    float x = p[0], y = p[1], z = p[2];
    int bin = (int)floorf((x - XMIN) * BININV);
    bin = min(max(bin, 0), NBINS - 1);           // clamp to EXTREME bins: keeps
                                                 // x-ordering invariant exact
    int a = s * BATCH + b;
    int slot = atomicAdd(&g_cnt[a * NBINS + bin], 1);
    if (slot < CAP) {
        float t2 = x * x + y * y + z * z;
        g_bins[(a * NBINS + bin) * CAP + slot] =
            make_float4(t2, -2.f * x, -2.f * y, -2.f * z);
    }
}

// ---- K3: branch-and-bound nearest-neighbor scan + full reduction ---------
__global__ __launch_bounds__(256)
void scan_kernel(float* __restrict__ out)
{
    extern __shared__ unsigned char sraw[];
    float4* cand = (float4*)sraw;                          // compacted candidates
    int*    cinc = (int*)(sraw + NPTS * sizeof(float4));   // incl prefix, cands
    int*    qinc = cinc + NBINS;                           // incl prefix, queries
    __shared__ float wsum[8];
    __shared__ int   is_last;

    int tid   = threadIdx.x;
    int bid   = blockIdx.x;
    int chunk = bid & (NCHUNK - 1);
    int b     = (bid >> 4) & 7;
    int dir   = bid >> 7;
    int qa = dir * BATCH + b;          // dir 0: queries = pred
    int ca = (1 - dir) * BATCH + b;    // dir 0: candidates = target

    if (tid < NBINS) {
        cinc[tid] = min(g_cnt[ca * NBINS + tid], CAP);
        qinc[tid] = min(g_cnt[qa * NBINS + tid], CAP);
    }
    __syncthreads();
    // Hillis-Steele inclusive scan over 128 bins
    for (int off = 1; off < NBINS; off <<= 1) {
        int vc = 0, vq = 0;
        if (tid < NBINS && tid >= off) { vc = cinc[tid - off]; vq = qinc[tid - off]; }
        __syncthreads();
        if (tid < NBINS && tid >= off) { cinc[tid] += vc; qinc[tid] += vq; }
        __syncthreads();
    }

    // stage candidates compacted into smem (coalesced global reads)
    for (int idx = tid; idx < NBINS * CAP; idx += 256) {
        int bin  = idx >> 8;            // CAP == 256
        int slot = idx & (CAP - 1);
        int st   = bin ? cinc[bin - 1] : 0;
        if (slot < cinc[bin] - st)
            cand[st + slot] = g_bins[ca * NBINS * CAP + idx];
    }
    __syncthreads();

    // this thread's query: gq-th entry in bucketed (x-sorted-by-bin) order
    int gq = chunk * QPB + tid;
    float myv = 0.0f;
    bool valid = gq < qinc[NBINS - 1];
    if (valid) {
        int qb = 0;                     // smallest bin with qinc[qb] > gq
        #pragma unroll
        for (int stp = 64; stp; stp >>= 1) {
            int nb = qb + stp;
            if (nb <= NBINS && qinc[nb - 1] <= gq) qb = nb;
        }
        int qslot = gq - (qb ? qinc[qb - 1] : 0);
        float4 qp = g_bins[(qa * NBINS + qb) * CAP + qslot];
        float p2 = qp.x;
        float qx = -0.5f * qp.y, qy = -0.5f * qp.z, qz = -0.5f * qp.w;

        float dmp = 1e30f;              // min of (d - p2)
        auto scanbin = [&](int bin) {
            int st = bin ? cinc[bin - 1] : 0;
            int en = cinc[bin];
            for (int i = st; i < en; i++) {
                float4 c = cand[i];
                float d = fmaf(c.y, qx, fmaf(c.z, qy, fmaf(c.w, qz, c.x)));
                dmp = fminf(dmp, d);
            }
        };
        scanbin(qb);
        int l = qb - 1, r = qb + 1;
        while (true) {
            float gl = (l >= 0)    ? (qx - (XMIN + (float)(l + 1) * BINW)) : 1e15f;
            float gr = (r < NBINS) ? ((XMIN + (float)r * BINW) - qx)       : 1e15f;
            if (gl <= gr) {
                if (gl * gl >= dmp + p2) break;   // nearer side pruned -> both pruned
                scanbin(l); l--;
            } else {
                if (gr * gr >= dmp + p2) break;
                scanbin(r); r++;
            }
        }
        myv = dmp + p2;
    }

    // block sum of per-query mins
    #pragma unroll
    for (int off = 16; off; off >>= 1)
        myv += __shfl_down_sync(0xffffffffu, myv, off);
    if ((tid & 31) == 0) wsum[tid >> 5] = myv;
    __syncthreads();

    if (tid == 0) {
        float s = 0.0f;
        #pragma unroll
        for (int w = 0; w < 8; w++) s += wsum[w];
        g_bsum[bid] = s;
        __threadfence();
        is_last = (atomicAdd(&g_tick, 1u) == GRID3 - 1);
    }
    __syncthreads();

    if (is_last && tid < 32) {
        __threadfence();
        float s = 0.0f;
        #pragma unroll
        for (int k = 0; k < GRID3 / 32; k++)
            s += *((volatile float*)&g_bsum[k * 32 + tid]);
        #pragma unroll
        for (int off = 16; off; off >>= 1)
            s += __shfl_down_sync(0xffffffffu, s, off);
        if (tid == 0) {
            out[0] = s * (1.0f / (float)(BATCH * NPTS));
            g_tick = 0;   // self-reset for next graph replay
        }
    }
}

extern "C" void kernel_launch(void* const* d_in, const int* in_sizes, int n_in,
                              void* d_out, int out_size)
{
    const float* pred   = (const float*)d_in[0];
    const float* target = (const float*)d_in[1];
    float* out = (float*)d_out;

    cudaFuncSetAttribute(scan_kernel,
                         cudaFuncAttributeMaxDynamicSharedMemorySize, SMEM3);

    zero_kernel<<<1, 256>>>();
    scatter_kernel<<<(2 * BATCH * NPTS) / 256, 256>>>(pred, target);
    scan_kernel<<<GRID3, 256, SMEM3>>>(out);
}

// round 11
// speedup vs baseline: 1.8631x; 1.8631x over previous
#include <cuda_runtime.h>

#define BATCH   8
#define NPTS    4096
#define THREADS 128
#define QBLK    8                        // queries per thread
#define QCH     (QBLK * THREADS)         // 1024 queries per block
#define QCHUNKS (NPTS / QCH)             // 4 query chunks per (dir,batch)
#define SPLIT   16                       // candidate splits
#define CTILE   (NPTS / SPLIT)           // 256 candidates per block
#define CPAIRS  (CTILE / 2)              // 128 packed candidate pairs
#define NQ      (2 * BATCH * NPTS)       // 65536 query slots (both dirs)
#define NBLK    (2 * BATCH * QCHUNKS * SPLIT)  // 1024 chamfer blocks

__device__ unsigned g_max[NQ];   // reversed order keys; 0 == +inf identity
__device__ unsigned g_tick;      // zero-init; self-reset each replay

// ---- f32x2 helpers -------------------------------------------------------
__device__ __forceinline__ unsigned long long pk(float lo, float hi) {
    unsigned long long r;
    asm("mov.b64 %0, {%1, %2};" : "=l"(r)
        : "r"(__float_as_uint(lo)), "r"(__float_as_uint(hi)));
    return r;
}
__device__ __forceinline__ unsigned long long fma2(
    unsigned long long a, unsigned long long b, unsigned long long c) {
    unsigned long long d;
    asm("fma.rn.f32x2 %0, %1, %2, %3;" : "=l"(d) : "l"(a), "l"(b), "l"(c));
    return d;
}
__device__ __forceinline__ void unpk(unsigned long long v, float& lo, float& hi) {
    unsigned a, b;
    asm("mov.b64 {%0, %1}, %2;" : "=r"(a), "=r"(b) : "l"(v));
    lo = __uint_as_float(a);
    hi = __uint_as_float(b);
}

// order-preserving float->uint key, REVERSED (smaller float -> larger key)
// so zero-initialized g_max is the identity for atomicMax
__device__ __forceinline__ unsigned rkey(float f) {
    unsigned u = __float_as_uint(f);
    unsigned k = (u >> 31) ? ~u : (u | 0x80000000u);
    return ~k;
}
__device__ __forceinline__ float rdecode(unsigned r) {
    unsigned k = ~r;
    unsigned u = (k >> 31) ? (k & 0x7FFFFFFFu) : ~k;
    return __uint_as_float(u);
}

// ---- single fused kernel: partial mins + ticket-counter final reduce -----
__global__ __launch_bounds__(THREADS, 4)
void chamfer_kernel(const float* __restrict__ pred,
                    const float* __restrict__ target,
                    float* __restrict__ out)
{
    // packed candidate pairs: sm[2k]=(t2 pair, -2x pair), sm[2k+1]=(-2y, -2z)
    __shared__ ulonglong2 sm[2 * CPAIRS];   // 4 KB
    __shared__ float      wsum[4];
    __shared__ int        is_last;

    int bid   = blockIdx.x;
    int s     = bid & (SPLIT - 1);
    int chunk = (bid >> 4) & (QCHUNKS - 1);
    int b     = (bid >> 6) & (BATCH - 1);
    int dir   = bid >> 9;

    const float* Q = dir ? target : pred;
    const float* C = dir ? pred   : target;

    int tid = threadIdx.x;

    // 8 query points per thread, stride-THREADS for coalescing
    int qbase = chunk * QCH + tid;
    unsigned long long pxp[QBLK], pyp[QBLK], pzp[QBLK];
    float p2[QBLK];
    #pragma unroll
    for (int q = 0; q < QBLK; q++) {
        const float* qp = Q + ((size_t)b * NPTS + qbase + q * THREADS) * 3;
        float px = qp[0], py = qp[1], pz = qp[2];
        p2[q]  = px * px + py * py + pz * pz;
        pxp[q] = pk(px, px);
        pyp[q] = pk(py, py);
        pzp[q] = pk(pz, pz);
    }

    // cooperative load + pack of this block's candidate tile (256 points)
    const float2* cb2 = (const float2*)(C + ((size_t)b * NPTS + s * CTILE) * 3);
    for (int k = tid; k < CPAIRS; k += THREADS) {
        float2 f0 = cb2[3 * k + 0];   // x0 y0
        float2 f1 = cb2[3 * k + 1];   // z0 x1
        float2 f2 = cb2[3 * k + 2];   // y1 z1
        float x0 = f0.x, y0 = f0.y, z0 = f1.x;
        float x1 = f1.y, y1 = f2.x, z1 = f2.y;
        float t20 = x0 * x0 + y0 * y0 + z0 * z0;
        float t21 = x1 * x1 + y1 * y1 + z1 * z1;
        sm[2 * k]     = make_ulonglong2(pk(t20, t21), pk(-2.f * x0, -2.f * x1));
        sm[2 * k + 1] = make_ulonglong2(pk(-2.f * y0, -2.f * y1), pk(-2.f * z0, -2.f * z1));
    }
    __syncthreads();

    float mlo[QBLK], mhi[QBLK];
    #pragma unroll
    for (int q = 0; q < QBLK; q++) { mlo[q] = 3.0e38f; mhi[q] = 3.0e38f; }

    #pragma unroll 2
    for (int k = 0; k < CPAIRS; k += 2) {
        ulonglong2 a0 = sm[2 * k + 0];
        ulonglong2 b0 = sm[2 * k + 1];
        ulonglong2 a1 = sm[2 * k + 2];
        ulonglong2 b1 = sm[2 * k + 3];
        #pragma unroll
        for (int q = 0; q < QBLK; q++) {
            unsigned long long v0 =
                fma2(b0.y, pzp[q], fma2(b0.x, pyp[q], fma2(a0.y, pxp[q], a0.x)));
            unsigned long long v1 =
                fma2(b1.y, pzp[q], fma2(b1.x, pyp[q], fma2(a1.y, pxp[q], a1.x)));
            float lo0, hi0, lo1, hi1;
            unpk(v0, lo0, hi0);
            unpk(v1, lo1, hi1);
            mlo[q] = fminf(mlo[q], fminf(lo0, lo1));
            mhi[q] = fminf(mhi[q], fminf(hi0, hi1));
        }
    }

    // fold into per-query global min (0 is the atomicMax identity -> no init)
    int qidx = (dir * BATCH + b) * NPTS + qbase;
    #pragma unroll
    for (int q = 0; q < QBLK; q++) {
        float m = fminf(mlo[q], mhi[q]) + p2[q];
        atomicMax(&g_max[qidx + q * THREADS], rkey(m));
    }

    // ---- ticket: last block performs the final reduction -----------------
    __threadfence();
    if (tid == 0)
        is_last = (atomicAdd(&g_tick, 1u) == NBLK - 1);
    __syncthreads();
    if (!is_last) return;

    __threadfence();
    // 65536 keys: 128 uint4 loads per thread, coalesced, L2-resident
    float a0 = 0.f, a1 = 0.f, a2 = 0.f, a3 = 0.f;
    volatile uint4* gm = (volatile uint4*)g_max;
    #pragma unroll 4
    for (int k = 0; k < NQ / (4 * THREADS); k++) {
        int i = k * THREADS + tid;
        uint4 v;
        v.x = gm[i].x; v.y = gm[i].y; v.z = gm[i].z; v.w = gm[i].w;
        ((uint4*)g_max)[i] = make_uint4(0u, 0u, 0u, 0u);  // reset for replay
        a0 += rdecode(v.x);
        a1 += rdecode(v.y);
        a2 += rdecode(v.z);
        a3 += rdecode(v.w);
    }
    float sum = (a0 + a1) + (a2 + a3);

    #pragma unroll
    for (int off = 16; off > 0; off >>= 1)
        sum += __shfl_down_sync(0xffffffffu, sum, off);
    if ((tid & 31) == 0) wsum[tid >> 5] = sum;
    __syncthreads();

    if (tid == 0) {
        float s = (wsum[0] + wsum[1]) + (wsum[2] + wsum[3]);
        out[0] = s * (1.0f / (float)(BATCH * NPTS));
        g_tick = 0;   // self-reset for next graph replay
    }
}

extern "C" void kernel_launch(void* const* d_in, const int* in_sizes, int n_in,
                              void* d_out, int out_size)
{
    const float* pred   = (const float*)d_in[0];
    const float* target = (const float*)d_in[1];
    float* out = (float*)d_out;

    chamfer_kernel<<<NBLK, THREADS>>>(pred, target, out);
}